// round 1
// baseline (speedup 1.0000x reference)
#include <cuda_runtime.h>
#include <math.h>

#define NROWS 8192
#define DCH 32
#define HSZ (NROWS * DCH)          // 262144 floats per H matrix
#define NSPLIT 8                   // j-splits for aggregation
#define HS_STRIDE 4112             // bytes per k-block in smem H tile (4096 + 16 pad -> distinct banks per k)
#define AD_STRIDE 36               // bytes per row in smem adj tile (conflict-free lane*9 bank walk)

// ---------------- device scratch (no allocation allowed) ----------------
__device__ float g_H[4 * HSZ];            // H[k][j][c]; k=0 is the all-zero "adj==0" branch
__device__ float g_Z[HSZ];                // layer-1 output (post bias+relu)
__device__ float g_PartZ[NSPLIT * HSZ];   // split-K partial sums
__device__ float g_colsum[32 * 32];       // column sums, padded 128B apart (LTS spread)

// ---------------- init: zero H[0] and colsum ----------------
__global__ void init_kernel() {
    int idx = blockIdx.x * blockDim.x + threadIdx.x;   // grid 1024 x 256 = 262144
    g_H[idx] = 0.0f;                                    // exactly the H[0] region
    if (idx < 1024) g_colsum[idx] = 0.0f;
}

// ---------------- H_k = Z @ w_k  (tiny: 8192x32x32 x3) ----------------
__global__ void compute_h_kernel(const float* __restrict__ Vin, int useZ,
                                 const float* __restrict__ w1,
                                 const float* __restrict__ w2,
                                 const float* __restrict__ w3) {
    const float* Z = useZ ? g_Z : Vin;
    int tid = threadIdx.x;
    int j = blockIdx.x * 8 + (tid >> 5);
    int c = tid & 31;
    float a1 = 0.f, a2 = 0.f, a3 = 0.f;
    const float* zr = Z + j * 32;
    #pragma unroll
    for (int i = 0; i < 32; i++) {
        float z = __ldg(zr + i);
        a1 = fmaf(z, __ldg(w1 + i * 32 + c), a1);
        a2 = fmaf(z, __ldg(w2 + i * 32 + c), a2);
        a3 = fmaf(z, __ldg(w3 + i * 32 + c), a3);
    }
    int o = j * 32 + c;
    g_H[HSZ + o]     = a1;
    g_H[2 * HSZ + o] = a2;
    g_H[3 * HSZ + o] = a3;
}

// ---------------- masked aggregation: PartZ[split][i][:] = sum_{j in split} H[adj[i][j]][j][:] ----------------
__global__ void __launch_bounds__(256, 2) aggregate_kernel(const int* __restrict__ adj) {
    __shared__ __align__(16) unsigned char adjS[256 * AD_STRIDE];   // 9216 B, adj values as bytes
    __shared__ __align__(16) unsigned char hS[4 * HS_STRIDE];       // 16448 B, H tile [k][jj=32][c=32] fp32

    const int tid  = threadIdx.x;
    const int lane = tid & 31;
    const int warp = tid >> 5;
    const int rowBase = blockIdx.x * 256;
    const int j0base  = blockIdx.y * (NROWS / NSPLIT);   // 1024 j per split

    // 32 channels as 16 packed f32x2 accumulators (acc[m] = channels 2m, 2m+1)
    unsigned long long acc[16];
    #pragma unroll
    for (int q = 0; q < 16; q++) acc[q] = 0ull;

    int4  padj[8];
    float4 ph[3];

    const int rsub = tid >> 3;          // 0..31
    const int jsub = (tid & 7) * 4;     // 0,4,...,28

    // prefetch tile 0 into registers
    {
        const int j0 = j0base;
        #pragma unroll
        for (int it = 0; it < 8; it++)
            padj[it] = *(const int4*)(adj + (size_t)(rowBase + rsub + it * 32) * NROWS + j0 + jsub);
        #pragma unroll
        for (int u = 0; u < 3; u++)     // k = u+1 (k=0 stays zero in smem)
            ph[u] = *(const float4*)(g_H + (u + 1) * HSZ + (j0 + rsub) * 32 + jsub);
    }

    for (int t = 0; t < 32; t++) {
        __syncthreads();
        // ---- stage prefetched tile into smem ----
        #pragma unroll
        for (int it = 0; it < 8; it++) {
            unsigned p1 = __byte_perm((unsigned)padj[it].x, (unsigned)padj[it].y, 0x0040);
            unsigned p2 = __byte_perm((unsigned)padj[it].z, (unsigned)padj[it].w, 0x0040);
            unsigned pk = __byte_perm(p1, p2, 0x5410);   // [x0,y0,z0,w0]
            *(unsigned*)(adjS + (rsub + it * 32) * AD_STRIDE + jsub) = pk;
        }
        if (t == 0) {   // k=0 block: zeros, written once (never overwritten)
            *(float4*)(hS + rsub * 128 + jsub * 4) = make_float4(0.f, 0.f, 0.f, 0.f);
        }
        #pragma unroll
        for (int u = 0; u < 3; u++)
            *(float4*)(hS + (u + 1) * HS_STRIDE + rsub * 128 + jsub * 4) = ph[u];
        __syncthreads();

        // ---- prefetch next tile (LDG latency hidden by compute below) ----
        if (t + 1 < 32) {
            const int j0 = j0base + (t + 1) * 32;
            #pragma unroll
            for (int it = 0; it < 8; it++)
                padj[it] = *(const int4*)(adj + (size_t)(rowBase + rsub + it * 32) * NROWS + j0 + jsub);
            #pragma unroll
            for (int u = 0; u < 3; u++)
                ph[u] = *(const float4*)(g_H + (u + 1) * HSZ + (j0 + rsub) * 32 + jsub);
        }

        // ---- inner compute: 32 j x (select H row, add 32 ch via 16 f32x2 adds) ----
        const unsigned char* ap = adjS + (warp * 32 + lane) * AD_STRIDE;
        #pragma unroll 8
        for (int jj = 0; jj < 32; jj++) {
            int a = ap[jj];
            const ulonglong2* hp = (const ulonglong2*)(hS + a * HS_STRIDE + jj * 128);
            #pragma unroll
            for (int q = 0; q < 8; q++) {
                ulonglong2 v = hp[q];
                asm("add.rn.f32x2 %0, %0, %1;" : "+l"(acc[2 * q])     : "l"(v.x));
                asm("add.rn.f32x2 %0, %0, %1;" : "+l"(acc[2 * q + 1]) : "l"(v.y));
            }
        }
    }

    const int myRow = rowBase + warp * 32 + lane;
    unsigned long long* op =
        (unsigned long long*)(g_PartZ + ((size_t)blockIdx.y * NROWS + myRow) * 32);
    #pragma unroll
    for (int q = 0; q < 16; q++) op[q] = acc[q];
}

// ---------------- combine splits + bias + relu; mode 0 -> g_Z, mode 1 -> column sums ----------------
__global__ void combine_kernel(const float* __restrict__ bias, int mode) {
    __shared__ float colacc[32];
    int tid = threadIdx.x;
    if (tid < 32) colacc[tid] = 0.f;
    __syncthreads();

    int gi  = blockIdx.x * 256 + tid;     // grid 256 x 256 = 8192 rows * 8 cgroups
    int row = gi >> 3;
    int c0  = (gi & 7) * 4;
    float4 s = make_float4(0.f, 0.f, 0.f, 0.f);
    #pragma unroll
    for (int sp = 0; sp < NSPLIT; sp++) {
        float4 p = *(const float4*)(g_PartZ + ((size_t)sp * NROWS + row) * 32 + c0);
        s.x += p.x; s.y += p.y; s.z += p.z; s.w += p.w;
    }
    s.x = fmaxf(s.x + __ldg(bias + c0 + 0), 0.f);
    s.y = fmaxf(s.y + __ldg(bias + c0 + 1), 0.f);
    s.z = fmaxf(s.z + __ldg(bias + c0 + 2), 0.f);
    s.w = fmaxf(s.w + __ldg(bias + c0 + 3), 0.f);

    if (mode == 0) {
        *(float4*)(g_Z + row * 32 + c0) = s;
    } else {
        atomicAdd(&colacc[c0 + 0], s.x);
        atomicAdd(&colacc[c0 + 1], s.y);
        atomicAdd(&colacc[c0 + 2], s.z);
        atomicAdd(&colacc[c0 + 3], s.w);
        __syncthreads();
        if (tid < 32) atomicAdd(&g_colsum[tid * 32], colacc[tid]);
    }
}

// ---------------- FC head: relu(s @ W0^T + b0) @ W1^T + b1 -> sigmoid ----------------
__global__ void fc_kernel(const float* __restrict__ W0, const float* __restrict__ b0,
                          const float* __restrict__ W1, const float* __restrict__ b1,
                          float* __restrict__ out) {
    int lane = threadIdx.x;
    __shared__ float s[32];
    s[lane] = g_colsum[lane * 32];
    __syncwarp();
    float acc = __ldg(b0 + lane);
    #pragma unroll
    for (int i = 0; i < 32; i++) acc = fmaf(s[i], __ldg(W0 + lane * 32 + i), acc);
    float y = fmaxf(acc, 0.f);
    float p = y * __ldg(W1 + lane);
    #pragma unroll
    for (int o = 16; o; o >>= 1) p += __shfl_xor_sync(0xffffffffu, p, o);
    if (lane == 0) out[0] = 1.0f / (1.0f + expf(-(p + __ldg(b1))));
}

// ---------------- launch ----------------
extern "C" void kernel_launch(void* const* d_in, const int* in_sizes, int n_in,
                              void* d_out, int out_size) {
    (void)in_sizes; (void)n_in; (void)out_size;
    const float* V    = (const float*)d_in[0];
    const int*   adj  = (const int*)  d_in[1];
    const float* w1_0 = (const float*)d_in[2];
    const float* w2_0 = (const float*)d_in[3];
    const float* w3_0 = (const float*)d_in[4];
    const float* gb_0 = (const float*)d_in[5];
    const float* w1_1 = (const float*)d_in[6];
    const float* w2_1 = (const float*)d_in[7];
    const float* w3_1 = (const float*)d_in[8];
    const float* gb_1 = (const float*)d_in[9];
    const float* fcW0 = (const float*)d_in[10];
    const float* fcb0 = (const float*)d_in[11];
    const float* fcW1 = (const float*)d_in[12];
    const float* fcb1 = (const float*)d_in[13];

    dim3 ag(NROWS / 256, NSPLIT);   // 32 x 8 = 256 CTAs

    init_kernel<<<1024, 256>>>();
    compute_h_kernel<<<1024, 256>>>(V, 0, w1_0, w2_0, w3_0);
    aggregate_kernel<<<ag, 256>>>(adj);
    combine_kernel<<<256, 256>>>(gb_0, 0);
    compute_h_kernel<<<1024, 256>>>(nullptr, 1, w1_1, w2_1, w3_1);
    aggregate_kernel<<<ag, 256>>>(adj);
    combine_kernel<<<256, 256>>>(gb_1, 1);
    fc_kernel<<<1, 32>>>(fcW0, fcb0, fcW1, fcb1, (float*)d_out);
}

// round 3
// speedup vs baseline: 2.1872x; 2.1872x over previous
#include <cuda_runtime.h>
#include <cuda_bf16.h>
#include <cstdint>
#include <math.h>

#define NROWS 8192
#define HSZ (NROWS * 32)
#define NSPLIT 4
#define JSPLIT (NROWS / NSPLIT)        // 2048 j per CTA
#define CHUNKJ 64
#define NCHUNK (JSPLIT / CHUNKJ)       // 32 chunks
#define PITCH 144                      // smem row pitch (bytes) for 128B of G data
#define MSTRIDE (64 * PITCH)           // 9216 per mask
#define BUFB (3 * MSTRIDE)             // 27648 per buffer
#define SMEM_DYN (2 * BUFB)            // 55296

// ---------------- device scratch ----------------
__device__ float g_Z[HSZ];
__device__ float g_PartZ[NSPLIT * HSZ];
__device__ float g_colsum[32 * 32];
__device__ __nv_bfloat16 g_GT[3 * 64 * NROWS];   // [k][cc][j]; cc<32 hi(c), cc>=32 lo(c-32)

// ---------------- helpers ----------------
__device__ __forceinline__ uint32_t smem_u32(const void* p) {
    uint32_t a;
    asm("{ .reg .u64 t; cvta.to.shared.u64 t, %1; cvt.u32.u64 %0, t; }" : "=r"(a) : "l"(p));
    return a;
}
__device__ __forceinline__ void cp16(uint32_t dst, const void* src) {
    asm volatile("cp.async.cg.shared.global [%0], [%1], 16;" :: "r"(dst), "l"(src) : "memory");
}
__device__ __forceinline__ void cp_commit() { asm volatile("cp.async.commit_group;" ::: "memory"); }
__device__ __forceinline__ void cp_wait1()  { asm volatile("cp.async.wait_group 1;" ::: "memory"); }
__device__ __forceinline__ void cp_wait0()  { asm volatile("cp.async.wait_group 0;" ::: "memory"); }

__device__ __forceinline__ void ldm4(uint32_t* r, uint32_t addr) {
    asm volatile("ldmatrix.sync.aligned.m8n8.x4.shared.b16 {%0,%1,%2,%3}, [%4];"
                 : "=r"(r[0]), "=r"(r[1]), "=r"(r[2]), "=r"(r[3]) : "r"(addr));
}
__device__ __forceinline__ void mma16816(float* c, const uint32_t* a, uint32_t b0, uint32_t b1) {
    asm volatile(
        "mma.sync.aligned.m16n8k16.row.col.f32.bf16.bf16.f32 "
        "{%0,%1,%2,%3}, {%4,%5,%6,%7}, {%8,%9}, {%0,%1,%2,%3};"
        : "+f"(c[0]), "+f"(c[1]), "+f"(c[2]), "+f"(c[3])
        : "r"(a[0]), "r"(a[1]), "r"(a[2]), "r"(a[3]), "r"(b0), "r"(b1));
}

// ---------------- init ----------------
__global__ void init_kernel() {
    int idx = blockIdx.x * blockDim.x + threadIdx.x;
    if (idx < 1024) g_colsum[idx] = 0.0f;
}

// ---------------- GT prep: G^T[k][cc][j] from (V or Z) @ w_k, bf16 hi/lo split ----------------
__global__ void gt_kernel(const float* __restrict__ Vin, int useZ,
                          const float* __restrict__ w1,
                          const float* __restrict__ w2,
                          const float* __restrict__ w3) {
    const float* Z = useZ ? g_Z : Vin;
    int tid = threadIdx.x, lane = tid & 31, w = tid >> 5;
    int j = blockIdx.x * 32 + lane;

    float z[32];
    #pragma unroll
    for (int q = 0; q < 8; q++) {
        float4 v = *(const float4*)(Z + (size_t)j * 32 + q * 4);
        z[q * 4 + 0] = v.x; z[q * 4 + 1] = v.y; z[q * 4 + 2] = v.z; z[q * 4 + 3] = v.w;
    }
    #pragma unroll
    for (int m = 0; m < 24; m++) {
        int idx = w * 24 + m;                // 0..191
        int k = idx >> 6;                    // 0..2
        int cc = idx & 63;
        int c = cc & 31;
        const float* wk = (k == 0) ? w1 : ((k == 1) ? w2 : w3);
        float h = 0.f;
        #pragma unroll
        for (int i = 0; i < 32; i++) h = fmaf(z[i], __ldg(wk + i * 32 + c), h);
        __nv_bfloat16 hi = __float2bfloat16(h);
        __nv_bfloat16 out = (cc < 32) ? hi : __float2bfloat16(h - __bfloat162float(hi));
        g_GT[(size_t)idx * NROWS + j] = out;
    }
}

// ---------------- masked aggregation: D^T = sum_k G_k^T @ M_k^T via mma.sync bf16 ----------------
__global__ void __launch_bounds__(256, 2) agg_kernel(const int* __restrict__ adj) {
    extern __shared__ __align__(128) unsigned char dyn[];
    const uint32_t sb = smem_u32(dyn);

    const int tid = threadIdx.x, lane = tid & 31, w = tid >> 5;
    const int g = lane >> 2, t = lane & 3;
    const int i0 = blockIdx.x * 128;
    const int j0 = blockIdx.y * JSPLIT;
    const int iw = i0 + w * 16;

    // ldmatrix per-lane address offset: lanes 0-7 tile0(cc,k), 8-15 tile1(cc+8),
    // 16-23 tile2(k+8), 24-31 tile3(both)
    const uint32_t lmo = (uint32_t)((lane & 7) * PITCH + ((lane >> 3) & 1) * (8 * PITCH)
                                    + ((lane >> 4) & 1) * 16);

    float acc[2][2][4];
    #pragma unroll
    for (int a = 0; a < 2; a++)
        #pragma unroll
        for (int b = 0; b < 2; b++)
            #pragma unroll
            for (int q = 0; q < 4; q++) acc[a][b][q] = 0.f;

    // ---- stage chunk 0 ----
    {
        const int jc = j0;
        #pragma unroll
        for (int q = 0; q < 6; q++) {
            int idx = tid + 256 * q;          // 0..1535
            int row = idx >> 3, seg = idx & 7;
            const void* src = (const void*)(g_GT + (size_t)row * NROWS + jc + seg * 8);
            uint32_t d = sb + (row >> 6) * MSTRIDE + (row & 63) * PITCH + seg * 16;
            cp16(d, src);
        }
        cp_commit();
    }

    for (int ch = 0; ch < NCHUNK; ch++) {
        if (ch + 1 < NCHUNK) {
            const int jc = j0 + (ch + 1) * CHUNKJ;
            const uint32_t db = sb + ((ch + 1) & 1) * BUFB;
            #pragma unroll
            for (int q = 0; q < 6; q++) {
                int idx = tid + 256 * q;
                int row = idx >> 3, seg = idx & 7;
                const void* src = (const void*)(g_GT + (size_t)row * NROWS + jc + seg * 8);
                uint32_t d = db + (row >> 6) * MSTRIDE + (row & 63) * PITCH + seg * 16;
                cp16(d, src);
            }
            cp_commit();
            cp_wait1();
        } else {
            cp_wait0();
        }
        __syncthreads();

        const uint32_t buf = sb + (ch & 1) * BUFB;
        #pragma unroll
        for (int ks = 0; ks < 4; ks++) {
            // A fragments: 3 masks x 4 m-tiles (cc 0-63)
            uint32_t afr[3][4][4];
            #pragma unroll
            for (int m = 0; m < 3; m++)
                #pragma unroll
                for (int mt = 0; mt < 4; mt++)
                    ldm4(afr[m][mt], buf + m * MSTRIDE + mt * (16 * PITCH) + ks * 32 + lmo);

            const int jb = j0 + ch * CHUNKJ + ks * 16;
            #pragma unroll
            for (int nt = 0; nt < 2; nt++) {
                const int* ap = adj + (size_t)(iw + nt * 8 + g) * NROWS + jb + 2 * t;
                int2 pa = *(const int2*)ap;
                int2 pb = *(const int2*)(ap + 8);
                uint32_t pk1 = __byte_perm((uint32_t)pa.x, (uint32_t)pa.y, 0x0040);
                uint32_t pk2 = __byte_perm((uint32_t)pb.x, (uint32_t)pb.y, 0x0040);
                #pragma unroll
                for (int m = 0; m < 3; m++) {
                    uint32_t kk = 0x01010101u * (m + 1);
                    uint32_t c1 = __vcmpeq4(pk1, kk);
                    uint32_t c2 = __vcmpeq4(pk2, kk);
                    uint32_t b0 = __byte_perm(c1, c1, 0x1100) & 0x3F803F80u;
                    uint32_t b1 = __byte_perm(c2, c2, 0x1100) & 0x3F803F80u;
                    #pragma unroll
                    for (int mt = 0; mt < 4; mt++)
                        mma16816(acc[nt][mt & 1], afr[m][mt], b0, b1);
                }
            }
        }
        __syncthreads();
    }

    // ---- epilogue: transpose D^T frags -> D[i][c] via smem, then coalesced store ----
    float* tp = (float*)dyn;   // 128 rows x 32 ch fp32 = 16KB (buffers no longer needed)
    #pragma unroll
    for (int nt = 0; nt < 2; nt++)
        #pragma unroll
        for (int mtc = 0; mtc < 2; mtc++) {
            int r0 = w * 16 + nt * 8 + 2 * t;
            int c0 = mtc * 16 + g;
            tp[(r0    ) * 32 + c0    ] = acc[nt][mtc][0];
            tp[(r0 + 1) * 32 + c0    ] = acc[nt][mtc][1];
            tp[(r0    ) * 32 + c0 + 8] = acc[nt][mtc][2];
            tp[(r0 + 1) * 32 + c0 + 8] = acc[nt][mtc][3];
        }
    __syncthreads();
    #pragma unroll
    for (int q = 0; q < 4; q++) {
        int idx = tid + 256 * q;          // 0..1023 float4s
        int r = idx >> 3, seg = idx & 7;
        float4 v = *(float4*)(tp + r * 32 + seg * 4);
        *(float4*)(g_PartZ + ((size_t)blockIdx.y * NROWS + i0 + r) * 32 + seg * 4) = v;
    }
}

// ---------------- combine splits + bias + relu; mode 0 -> g_Z, mode 1 -> column sums ----------------
__global__ void combine_kernel(const float* __restrict__ bias, int mode) {
    __shared__ float colacc[32];
    int tid = threadIdx.x;
    if (tid < 32) colacc[tid] = 0.f;
    __syncthreads();

    int gi  = blockIdx.x * 256 + tid;
    int row = gi >> 3;
    int c0  = (gi & 7) * 4;
    float4 s = make_float4(0.f, 0.f, 0.f, 0.f);
    #pragma unroll
    for (int sp = 0; sp < NSPLIT; sp++) {
        float4 p = *(const float4*)(g_PartZ + ((size_t)sp * NROWS + row) * 32 + c0);
        s.x += p.x; s.y += p.y; s.z += p.z; s.w += p.w;
    }
    s.x = fmaxf(s.x + __ldg(bias + c0 + 0), 0.f);
    s.y = fmaxf(s.y + __ldg(bias + c0 + 1), 0.f);
    s.z = fmaxf(s.z + __ldg(bias + c0 + 2), 0.f);
    s.w = fmaxf(s.w + __ldg(bias + c0 + 3), 0.f);

    if (mode == 0) {
        *(float4*)(g_Z + (size_t)row * 32 + c0) = s;
    } else {
        atomicAdd(&colacc[c0 + 0], s.x);
        atomicAdd(&colacc[c0 + 1], s.y);
        atomicAdd(&colacc[c0 + 2], s.z);
        atomicAdd(&colacc[c0 + 3], s.w);
        __syncthreads();
        if (tid < 32) atomicAdd(&g_colsum[tid * 32], colacc[tid]);
    }
}

// ---------------- FC head ----------------
__global__ void fc_kernel(const float* __restrict__ W0, const float* __restrict__ b0,
                          const float* __restrict__ W1, const float* __restrict__ b1,
                          float* __restrict__ out) {
    int lane = threadIdx.x;
    __shared__ float s[32];
    s[lane] = g_colsum[lane * 32];
    __syncwarp();
    float acc = __ldg(b0 + lane);
    #pragma unroll
    for (int i = 0; i < 32; i++) acc = fmaf(s[i], __ldg(W0 + lane * 32 + i), acc);
    float y = fmaxf(acc, 0.f);
    float p = y * __ldg(W1 + lane);
    #pragma unroll
    for (int o = 16; o; o >>= 1) p += __shfl_xor_sync(0xffffffffu, p, o);
    if (lane == 0) out[0] = 1.0f / (1.0f + expf(-(p + __ldg(b1))));
}

// ---------------- launch ----------------
extern "C" void kernel_launch(void* const* d_in, const int* in_sizes, int n_in,
                              void* d_out, int out_size) {
    (void)in_sizes; (void)n_in; (void)out_size;
    const float* V    = (const float*)d_in[0];
    const int*   adj  = (const int*)  d_in[1];
    const float* w1_0 = (const float*)d_in[2];
    const float* w2_0 = (const float*)d_in[3];
    const float* w3_0 = (const float*)d_in[4];
    const float* gb_0 = (const float*)d_in[5];
    const float* w1_1 = (const float*)d_in[6];
    const float* w2_1 = (const float*)d_in[7];
    const float* w3_1 = (const float*)d_in[8];
    const float* gb_1 = (const float*)d_in[9];
    const float* fcW0 = (const float*)d_in[10];
    const float* fcb0 = (const float*)d_in[11];
    const float* fcW1 = (const float*)d_in[12];
    const float* fcb1 = (const float*)d_in[13];

    cudaFuncSetAttribute(agg_kernel, cudaFuncAttributeMaxDynamicSharedMemorySize, SMEM_DYN);

    dim3 ag(NROWS / 128, NSPLIT);   // 64 x 4 = 256 CTAs

    init_kernel<<<4, 256>>>();
    gt_kernel<<<256, 256>>>(V, 0, w1_0, w2_0, w3_0);
    agg_kernel<<<ag, 256, SMEM_DYN>>>(adj);
    combine_kernel<<<256, 256>>>(gb_0, 0);
    gt_kernel<<<256, 256>>>(nullptr, 1, w1_1, w2_1, w3_1);
    agg_kernel<<<ag, 256, SMEM_DYN>>>(adj);
    combine_kernel<<<256, 256>>>(gb_1, 1);
    fc_kernel<<<1, 32>>>(fcW0, fcb0, fcW1, fcb1, (float*)d_out);
}